// round 13
// baseline (speedup 1.0000x reference)
#include <cuda_runtime.h>

#define NS   4
#define NP   4096      // 64*64 pixels
#define NSZ  24
#define CN   64

// Output layout (flat concat of the 5-tuple, f32)
#define OFF_R0 0
#define OFF_BL 12288
#define OFF_IV 24576
#define OFF_WT 73728
#define OFF_CF 466944

#define VCHUNK 12
#define NVCH   43      // ceil(515/12)

// 4-row chunks: tile = 6 rows x 66 cols per channel
#define TW   66
#define TS4  396

// Scratch
__device__ float  g_ceT [NS*NP*CN];     // flow features, pixel-major [s][p][c]
__device__ float  g_ctxT[NS*NP*CN];     // ctx features,  pixel-major
__device__ float4 g_rec [NS*NP];        // {dotW(ce 0..31), dotC, sv0, sv1}
__device__ float4 g_rec2[NS*NP];        // {dotW(ce 32..63 + sf), dotC, sv2, 0}
__device__ float  g_ictx[NS*CN*NP];     // interp_ctx, channel-major
__device__ float  g_psv [NS*CN*NP];     // psv_feat,   channel-major
__device__ float  g_clog[NS*NP];
__device__ float  g_vpart[NVCH*3*NP];

__device__ __forceinline__ float wsum(float v){
  #pragma unroll
  for (int o = 16; o; o >>= 1) v += __shfl_xor_sync(0xFFFFFFFFu, v, o);
  return v;
}
__device__ __forceinline__ float wmax(float v){
  #pragma unroll
  for (int o = 16; o; o >>= 1) v = fmaxf(v, __shfl_xor_sync(0xFFFFFFFFu, v, o));
  return v;
}

__device__ __forceinline__ void fma16(float acc[16], const float* wbase, float v){
  const float4* w4 = (const float4*)wbase;
  float4 a = w4[0], b = w4[1], c = w4[2], d = w4[3];
  acc[0]=fmaf(a.x,v,acc[0]);   acc[1]=fmaf(a.y,v,acc[1]);
  acc[2]=fmaf(a.z,v,acc[2]);   acc[3]=fmaf(a.w,v,acc[3]);
  acc[4]=fmaf(b.x,v,acc[4]);   acc[5]=fmaf(b.y,v,acc[5]);
  acc[6]=fmaf(b.z,v,acc[6]);   acc[7]=fmaf(b.w,v,acc[7]);
  acc[8]=fmaf(c.x,v,acc[8]);   acc[9]=fmaf(c.y,v,acc[9]);
  acc[10]=fmaf(c.z,v,acc[10]); acc[11]=fmaf(c.w,v,acc[11]);
  acc[12]=fmaf(d.x,v,acc[12]); acc[13]=fmaf(d.y,v,acc[13]);
  acc[14]=fmaf(d.z,v,acc[14]); acc[15]=fmaf(d.w,v,acc[15]);
}

// ---------------------------------------------------------------------------
// K1: flowRefNet conv 18->64, relu, pixel-major + per-pixel dot records.
// grid (16 rowchunks of 4, 2 oc-halves, 4 src), block 256 (4 rows x 64 cols)
// ---------------------------------------------------------------------------
__global__ void __launch_bounds__(256) k_flow(
    const float* __restrict__ sf, const float* __restrict__ sv,
    const float* __restrict__ wv,
    const float* __restrict__ fw, const float* __restrict__ fb,
    const float* __restrict__ ww, const float* __restrict__ cw){
  __shared__ float s_in[18*TS4];
  __shared__ __align__(16) float buf[4352];
  __shared__ float s_wc[140];
  int rc = blockIdx.x, half = blockIdx.y, bs = blockIdx.z;
  int tid = threadIdx.x, r0 = rc*4;

  for (int i = tid; i < 18*TS4; i += 256){
    int c = i/TS4, rem = i - c*TS4, ry = rem/TW, rx = rem - ry*TW;
    int gy = r0 - 1 + ry, gx = rx - 1;
    float v = 0.f;
    if ((unsigned)gy < 64u && (unsigned)gx < 64u){
      const float* src = (c < 6) ? sf + (bs*6 + c)*NP
                       : (c < 9) ? sv + (bs*3 + (c-6))*NP
                                 : wv + (bs*9 + (c-9))*NP;
      v = src[gy*64 + gx];
    }
    s_in[i] = v;
  }
  for (int i = tid; i < 140; i += 256) s_wc[i] = (i < 70) ? ww[i] : cw[i-70];
  __syncthreads();

  int ly = tid >> 6, lx = tid & 63;
  int p = (r0 + ly)*64 + lx;
  int tl = ly*TW + lx;
  float dW = 0.f, dC = 0.f;

  #pragma unroll 1
  for (int sub = 0; sub < 2; sub++){
    int oc0 = half*32 + sub*16;
    for (int i = tid; i < 2592; i += 256){
      int j = i & 15, ct = i >> 4;
      buf[i] = fw[(oc0 + j)*162 + ct];
    }
    __syncthreads();
    float acc[16];
    #pragma unroll
    for (int j = 0; j < 16; j++) acc[j] = fb[oc0 + j];
    #pragma unroll 1
    for (int c = 0; c < 18; c++){
      const float* cin = s_in + c*TS4 + tl;
      float v[9];
      #pragma unroll
      for (int ky = 0; ky < 3; ky++)
        #pragma unroll
        for (int kx = 0; kx < 3; kx++) v[ky*3+kx] = cin[ky*TW + kx];
      #pragma unroll
      for (int t = 0; t < 9; t++) fma16(acc, buf + (c*9 + t)*16, v[t]);
    }
    __syncthreads();
    #pragma unroll
    for (int j = 0; j < 16; j++){
      float r = fmaxf(acc[j], 0.f);
      dW = fmaf(s_wc[6 + oc0 + j],  r, dW);
      dC = fmaf(s_wc[76 + oc0 + j], r, dC);
      buf[tid*17 + j] = r;
    }
    __syncthreads();
    for (int i = tid; i < 4096; i += 256){
      int pl = i >> 4, j = i & 15;
      g_ceT[(bs*NP + r0*64 + pl)*64 + oc0 + j] = buf[pl*17 + j];
    }
    __syncthreads();
  }

  int cofs = (ly+1)*TW + (lx+1);
  if (half == 0){
    g_rec[bs*NP + p] = make_float4(dW, dC, s_in[6*TS4 + cofs], s_in[7*TS4 + cofs]);
  } else {
    #pragma unroll
    for (int j = 0; j < 6; j++){
      float t = s_in[j*TS4 + cofs];
      dW = fmaf(s_wc[j],      t, dW);
      dC = fmaf(s_wc[70 + j], t, dC);
    }
    g_rec2[bs*NP + p] = make_float4(dW, dC, s_in[8*TS4 + cofs], 0.f);
  }
}

// ---------------------------------------------------------------------------
// K1b: ctxNet conv 3->64, relu, pixel-major. grid (16,2,4), block 256.
// Runs concurrently with k_flow on a side stream.
// ---------------------------------------------------------------------------
__global__ void __launch_bounds__(256) k_ctx(
    const float* __restrict__ sv, const float* __restrict__ cxw,
    const float* __restrict__ cxb){
  __shared__ float s_in[3*TS4];
  __shared__ __align__(16) float s_w[27*32];
  __shared__ float s_out[256*33];
  int rc = blockIdx.x, half = blockIdx.y, bs = blockIdx.z;
  int tid = threadIdx.x, r0 = rc*4;
  int oc0 = half*32;

  for (int i = tid; i < 3*TS4; i += 256){
    int c = i/TS4, rem = i - c*TS4, ry = rem/TW, rx = rem - ry*TW;
    int gy = r0 - 1 + ry, gx = rx - 1;
    s_in[i] = ((unsigned)gy < 64u && (unsigned)gx < 64u)
              ? sv[(bs*3 + c)*NP + gy*64 + gx] : 0.f;
  }
  for (int i = tid; i < 864; i += 256){
    int j = i & 31, ct = i >> 5;
    s_w[ct*32 + j] = cxw[(oc0 + j)*27 + ct];
  }
  __syncthreads();

  int ly = tid >> 6, lx = tid & 63;
  int tl = ly*TW + lx;
  float acc[32];
  #pragma unroll
  for (int j = 0; j < 32; j++) acc[j] = cxb[oc0 + j];
  #pragma unroll
  for (int c = 0; c < 3; c++){
    const float* cin = s_in + c*TS4 + tl;
    float v[9];
    #pragma unroll
    for (int ky = 0; ky < 3; ky++)
      #pragma unroll
      for (int kx = 0; kx < 3; kx++) v[ky*3+kx] = cin[ky*TW + kx];
    #pragma unroll
    for (int t = 0; t < 9; t++){
      fma16(acc,      s_w + (c*9 + t)*32,      v[t]);
      fma16(acc + 16, s_w + (c*9 + t)*32 + 16, v[t]);
    }
  }
  #pragma unroll
  for (int j = 0; j < 32; j++) s_out[tid*33 + j] = fmaxf(acc[j], 0.f);
  __syncthreads();
  for (int i = tid; i < 8192; i += 256){
    int pl = i >> 5, j = i & 31;
    g_ctxT[(bs*NP + r0*64 + pl)*64 + oc0 + j] = s_out[pl*33 + j];
  }
}

// ---------------------------------------------------------------------------
// K2: fused epipolar gather + logits + softmax + interps. grid 2048, block 256
// ---------------------------------------------------------------------------
__global__ void __launch_bounds__(256) k_epi(
    const int* __restrict__ nxy,
    const float* __restrict__ spa, const float* __restrict__ ang,
    const float* __restrict__ ww,  const float* __restrict__ wb,
    const float* __restrict__ cw,  const float* __restrict__ cb,
    float* __restrict__ out){
  __shared__ float s_ww[206], s_cw[206];
  __shared__ float s_sa[8][NSZ*9];
  int tid = threadIdx.x;
  for (int i = tid; i < 206; i += 256){ s_ww[i] = ww[i]; s_cw[i] = cw[i]; }

  int gp0 = blockIdx.x*8;
  int bs = gp0 >> 12, p0 = gp0 & 4095;

  for (int i = tid; i < 1536; i += 256){
    int pp = i & 7;
    int n  = (i >> 3) % 24;
    int j  = i / 192;
    const float* src = (j < 2) ? spa + ((bs*2 + j)*NSZ + n)*NP
                               : ang + ((bs*6 + (j-2))*NSZ + n)*NP;
    s_sa[pp][n*9 + j] = src[p0 + pp];
  }
  __syncthreads();

  int warp = tid >> 5, lane = tid & 31;
  int p = p0 + warp;
  bool act = lane < NSZ;

  int idx = 0;
  if (act){
    int e = lane / 3, k = lane % 3;
    const int* q = nxy + ((bs*NP + p)*8 + e)*2;
    int xi = min(max(q[0], 0), 63);
    int yi = min(max(q[1] + (k - 1), 0), 63);
    idx = yi*64 + xi;
  }

  float mylogit = 0.f, myclog = 0.f, sv0 = 0.f, sv1 = 0.f, sv2 = 0.f;
  if (act){
    float4 A = g_rec [bs*NP + idx];
    float4 B = g_rec2[bs*NP + idx];
    mylogit = A.x + B.x;  myclog = A.y + B.y;
    sv0 = A.z; sv1 = A.w; sv2 = B.z;
    #pragma unroll
    for (int j = 0; j < 8; j++){
      float t = s_sa[warp][lane*9 + j];
      mylogit = fmaf(s_ww[198 + j], t, mylogit);
      myclog  = fmaf(s_cw[198 + j], t, myclog);
    }
  }

  const float* ceT = g_ceT + (size_t)bs*NP*CN;
  float a0 = 0.f, a1 = 0.f, sq0 = 0.f, sq1 = 0.f;
  #pragma unroll 4
  for (int n = 0; n < NSZ; n++){
    int ix = __shfl_sync(0xFFFFFFFFu, idx, n);
    float u0 = ceT[ix*CN + lane];
    float u1 = ceT[ix*CN + 32 + lane];
    a0 += u0; sq0 = fmaf(u0, u0, sq0);
    a1 += u1; sq1 = fmaf(u1, u1, sq1);
  }
  float mu0 = a0*(1.f/24.f), mu1 = a1*(1.f/24.f);
  float vr0 = (sq0 - 24.f*mu0*mu0)*(1.f/23.f);
  float vr1 = (sq1 - 24.f*mu1*mu1)*(1.f/23.f);
  float mw = s_ww[70+lane]*mu0 + s_ww[102+lane]*mu1 + s_ww[134+lane]*vr0 + s_ww[166+lane]*vr1;
  float mc = s_cw[70+lane]*mu0 + s_cw[102+lane]*mu1 + s_cw[134+lane]*vr0 + s_cw[166+lane]*vr1;
  mw = wsum(mw); mc = wsum(mc);
  mylogit += mw + wb[0];
  myclog  += mc + cb[0];

  float m  = wmax(act ? mylogit : -1e30f);
  float e  = act ? __expf(mylogit - m) : 0.f;
  float se = wsum(e);
  float wgt = e / se;
  if (act) out[OFF_WT + (bs*NP + p)*NSZ + lane] = wgt;

  float cs = wsum(act ? wgt*myclog : 0.f);
  if (lane == 0) g_clog[bs*NP + p] = cs;

  float r0 = wsum(act ? wgt*sv0 : 0.f);
  float r1 = wsum(act ? wgt*sv1 : 0.f);
  float r2 = wsum(act ? wgt*sv2 : 0.f);
  if (lane == 0){
    out[OFF_IV + (bs*3 + 0)*NP + p] = r0;
    out[OFF_IV + (bs*3 + 1)*NP + p] = r1;
    out[OFF_IV + (bs*3 + 2)*NP + p] = r2;
  }

  const float* ctxT = g_ctxT + (size_t)bs*NP*CN;
  float acc0 = 0.f, acc1 = 0.f;
  #pragma unroll 4
  for (int n = 0; n < NSZ; n++){
    int ix = __shfl_sync(0xFFFFFFFFu, idx, n);
    float wn = __shfl_sync(0xFFFFFFFFu, wgt, n);
    acc0 = fmaf(wn, ctxT[ix*CN + lane], acc0);
    acc1 = fmaf(wn, ctxT[ix*CN + 32 + lane], acc1);
  }
  g_ictx[(bs*CN + lane)*NP + p]      = acc0;
  g_ictx[(bs*CN + 32 + lane)*NP + p] = acc1;
}

// ---------------------------------------------------------------------------
// K3: psvNet conv 6->64 per depth, relu, mean over D=8; blended computed
// inline from g_clog + interp_view during halo staging. Designated blocks
// (bs==0 && half==0) emit OFF_BL / OFF_CF. grid (16,2,4), block 256.
// ---------------------------------------------------------------------------
__global__ void __launch_bounds__(256) k_psv(
    const float* __restrict__ psvs, const float* __restrict__ pw,
    const float* __restrict__ pb, float* __restrict__ out){
  __shared__ float s_bl[3*TS4];
  __shared__ float s_ps[24*TS4];
  __shared__ __align__(16) float s_w[864];
  int rc = blockIdx.x, half = blockIdx.y, bs = blockIdx.z;
  int tid = threadIdx.x, r0 = rc*4;

  // blended staging: conf softmax over sources + blend per halo pixel
  for (int i = tid; i < TS4; i += 256){
    int ry = i/TW, rx = i - ry*TW;
    int gy = r0 - 1 + ry, gx = rx - 1;
    float b0 = 0.f, b1 = 0.f, b2 = 0.f;
    if ((unsigned)gy < 64u && (unsigned)gx < 64u){
      int ip = gy*64 + gx;
      float c0 = g_clog[ip],        c1 = g_clog[NP + ip];
      float c2 = g_clog[2*NP + ip], c3 = g_clog[3*NP + ip];
      float mm = fmaxf(fmaxf(c0, c1), fmaxf(c2, c3));
      float e0 = __expf(c0 - mm), e1 = __expf(c1 - mm);
      float e2 = __expf(c2 - mm), e3 = __expf(c3 - mm);
      float inv = 1.f/(e0 + e1 + e2 + e3);
      float f0 = e0*inv, f1 = e1*inv, f2 = e2*inv, f3 = e3*inv;
      b0 = f0*out[OFF_IV + 0*NP + ip] + f1*out[OFF_IV + 3*NP + ip]
         + f2*out[OFF_IV + 6*NP + ip] + f3*out[OFF_IV + 9*NP + ip];
      b1 = f0*out[OFF_IV + 1*NP + ip] + f1*out[OFF_IV + 4*NP + ip]
         + f2*out[OFF_IV + 7*NP + ip] + f3*out[OFF_IV + 10*NP + ip];
      b2 = f0*out[OFF_IV + 2*NP + ip] + f1*out[OFF_IV + 5*NP + ip]
         + f2*out[OFF_IV + 8*NP + ip] + f3*out[OFF_IV + 11*NP + ip];
    }
    s_bl[i] = b0; s_bl[TS4 + i] = b1; s_bl[2*TS4 + i] = b2;
  }
  for (int i = tid; i < 24*TS4; i += 256){
    int cd = i/TS4, rem = i - cd*TS4, ry = rem/TW, rx = rem - ry*TW;
    int c = cd >> 3, d = cd & 7;
    int gy = r0 - 1 + ry, gx = rx - 1;
    s_ps[i] = ((unsigned)gy < 64u && (unsigned)gx < 64u)
              ? psvs[(((bs*3 + c)*8) + d)*NP + gy*64 + gx] : 0.f;
  }

  int ly = tid >> 6, lx = tid & 63;
  int p = (r0 + ly)*64 + lx;
  int tl = ly*TW + lx;

  #pragma unroll 1
  for (int sub = 0; sub < 2; sub++){
    int oc0 = half*32 + sub*16;
    if (sub) __syncthreads();
    for (int i = tid; i < 864; i += 256){
      int j = i & 15, ct = i >> 4;
      s_w[i] = pw[(oc0 + j)*54 + ct];
    }
    __syncthreads();

    float blp[16];
    #pragma unroll
    for (int j = 0; j < 16; j++) blp[j] = pb[oc0 + j];
    #pragma unroll
    for (int c = 0; c < 3; c++){
      const float* cin = s_bl + c*TS4 + tl;
      float v[9];
      #pragma unroll
      for (int ky = 0; ky < 3; ky++)
        #pragma unroll
        for (int kx = 0; kx < 3; kx++) v[ky*3+kx] = cin[ky*TW + kx];
      #pragma unroll
      for (int t = 0; t < 9; t++) fma16(blp, s_w + ((3 + c)*9 + t)*16, v[t]);
    }
    float oacc[16];
    #pragma unroll
    for (int j = 0; j < 16; j++) oacc[j] = 0.f;
    #pragma unroll 1
    for (int d = 0; d < 8; d++){
      float pv[16];
      #pragma unroll
      for (int j = 0; j < 16; j++) pv[j] = blp[j];
      #pragma unroll
      for (int c = 0; c < 3; c++){
        const float* cin = s_ps + (c*8 + d)*TS4 + tl;
        float v[9];
        #pragma unroll
        for (int ky = 0; ky < 3; ky++)
          #pragma unroll
          for (int kx = 0; kx < 3; kx++) v[ky*3+kx] = cin[ky*TW + kx];
        #pragma unroll
        for (int t = 0; t < 9; t++) fma16(pv, s_w + (c*9 + t)*16, v[t]);
      }
      #pragma unroll
      for (int j = 0; j < 16; j++) oacc[j] += fmaxf(pv[j], 0.f);
    }
    #pragma unroll
    for (int j = 0; j < 16; j++)
      g_psv[(bs*CN + oc0 + j)*NP + p] = oacc[j] * 0.125f;
  }

  // designated blocks emit blended_img + confs
  if (bs == 0 && half == 0){
    float c0 = g_clog[p],        c1 = g_clog[NP + p];
    float c2 = g_clog[2*NP + p], c3 = g_clog[3*NP + p];
    float mm = fmaxf(fmaxf(c0, c1), fmaxf(c2, c3));
    float e0 = __expf(c0 - mm), e1 = __expf(c1 - mm);
    float e2 = __expf(c2 - mm), e3 = __expf(c3 - mm);
    float inv = 1.f/(e0 + e1 + e2 + e3);
    out[OFF_CF + p]        = e0*inv;
    out[OFF_CF + NP + p]   = e1*inv;
    out[OFF_CF + 2*NP + p] = e2*inv;
    out[OFF_CF + 3*NP + p] = e3*inv;
    int cofs = (ly+1)*TW + (lx+1);
    out[OFF_BL + p]        = s_bl[cofs];
    out[OFF_BL + NP + p]   = s_bl[TS4 + cofs];
    out[OFF_BL + 2*NP + p] = s_bl[2*TS4 + cofs];
  }
}

// ---------------------------------------------------------------------------
// K5: vref conv 515->3, ic-chunked (12). mode 0: z=1+by (ictx-only chunks,
// depends only on k_epi). mode 1: z=0 or 20+by (blended/psv chunks).
// grid (16, 20|23), block 256.
// ---------------------------------------------------------------------------
__global__ void __launch_bounds__(256) k_vref(
    const float* __restrict__ vw, const float* __restrict__ vb,
    const float* __restrict__ out, int mode){
  __shared__ float s_in[VCHUNK*TS4];
  __shared__ __align__(16) float s_w[VCHUNK*9*4];
  int rc = blockIdx.x;
  int z = (mode == 0) ? (1 + blockIdx.y)
                      : ((blockIdx.y == 0) ? 0 : 20 + blockIdx.y);
  int tid = threadIdx.x, r0 = rc*4;
  int ic0 = z*VCHUNK;
  int nch = min(VCHUNK, 515 - ic0);

  for (int i = tid; i < nch*TS4; i += 256){
    int c = i/TS4, rem = i - c*TS4, ry = rem/TW, rx = rem - ry*TW;
    int ic = ic0 + c;
    int gy = r0 - 1 + ry, gx = rx - 1;
    float v = 0.f;
    if ((unsigned)gy < 64u && (unsigned)gx < 64u){
      const float* src = (ic < 3)   ? out + OFF_BL + ic*NP
                       : (ic < 259) ? g_ictx + (ic - 3)*NP
                                    : g_psv  + (ic - 259)*NP;
      v = src[gy*64 + gx];
    }
    s_in[i] = v;
  }
  for (int i = tid; i < nch*9*4; i += 256){
    int oc = i & 3, ct = i >> 2;
    s_w[i] = (oc < 3) ? vw[(oc*515 + ic0)*9 + ct] : 0.f;
  }
  __syncthreads();

  int ly = tid >> 6, lx = tid & 63;
  int p = (r0 + ly)*64 + lx;
  int tl = ly*TW + lx;
  float acc0 = (z == 0) ? vb[0] : 0.f;
  float acc1 = (z == 0) ? vb[1] : 0.f;
  float acc2 = (z == 0) ? vb[2] : 0.f;
  #pragma unroll 1
  for (int c = 0; c < nch; c++){
    const float* cin = s_in + c*TS4 + tl;
    float v[9];
    #pragma unroll
    for (int ky = 0; ky < 3; ky++)
      #pragma unroll
      for (int kx = 0; kx < 3; kx++) v[ky*3+kx] = cin[ky*TW + kx];
    #pragma unroll
    for (int t = 0; t < 9; t++){
      float4 w = *(const float4*)(s_w + (c*9 + t)*4);
      acc0 = fmaf(w.x, v[t], acc0);
      acc1 = fmaf(w.y, v[t], acc1);
      acc2 = fmaf(w.z, v[t], acc2);
    }
  }
  g_vpart[(z*3 + 0)*NP + p] = acc0;
  g_vpart[(z*3 + 1)*NP + p] = acc1;
  g_vpart[(z*3 + 2)*NP + p] = acc2;
}

__global__ void __launch_bounds__(128) k_vfin(float* __restrict__ out){
  int i = blockIdx.x*128 + threadIdx.x;   // 0..12287
  float a = 0.f;
  #pragma unroll
  for (int z = 0; z < NVCH; z++) a += g_vpart[z*3*NP + i];
  out[OFF_R0 + i] = a;
}

// ---------------------------------------------------------------------------
// Side stream + events, created at static init.
// ---------------------------------------------------------------------------
struct HxAsync {
  cudaStream_t s1;
  cudaEvent_t e_root, e_ctx, e_epi, e_vA;
  HxAsync(){
    cudaStreamCreateWithFlags(&s1, cudaStreamNonBlocking);
    cudaEventCreateWithFlags(&e_root, cudaEventDisableTiming);
    cudaEventCreateWithFlags(&e_ctx,  cudaEventDisableTiming);
    cudaEventCreateWithFlags(&e_epi,  cudaEventDisableTiming);
    cudaEventCreateWithFlags(&e_vA,   cudaEventDisableTiming);
  }
};
static HxAsync hx;

// ---------------------------------------------------------------------------
extern "C" void kernel_launch(void* const* d_in, const int* in_sizes, int n_in,
                              void* d_out, int out_size){
  const float* sv   = (const float*)d_in[0];
  const float* sf   = (const float*)d_in[1];
  const float* psvs = (const float*)d_in[2];
  const float* wv   = (const float*)d_in[3];
  const int*   nxy  = (const int*)  d_in[5];
  const float* spa  = (const float*)d_in[6];
  const float* ang  = (const float*)d_in[7];
  const float* flow_w = (const float*)d_in[9];
  const float* flow_b = (const float*)d_in[10];
  const float* ctx_w  = (const float*)d_in[11];
  const float* ctx_b  = (const float*)d_in[12];
  const float* wnet_w = (const float*)d_in[13];
  const float* wnet_b = (const float*)d_in[14];
  const float* cnet_w = (const float*)d_in[15];
  const float* cnet_b = (const float*)d_in[16];
  const float* psv_w  = (const float*)d_in[17];
  const float* psv_b  = (const float*)d_in[18];
  const float* vref_w = (const float*)d_in[19];
  const float* vref_b = (const float*)d_in[20];
  float* out = (float*)d_out;
  cudaStream_t s0 = (cudaStream_t)0;

  // fork: ctx runs concurrently with flow on side stream
  cudaEventRecord(hx.e_root, s0);
  cudaStreamWaitEvent(hx.s1, hx.e_root, 0);

  k_flow<<<dim3(16, 2, 4), 256, 0, s0>>>(sf, sv, wv, flow_w, flow_b,
                                         wnet_w, cnet_w);
  k_ctx <<<dim3(16, 2, 4), 256, 0, hx.s1>>>(sv, ctx_w, ctx_b);

  // join: epi needs both flow (s0 order) and ctx
  cudaEventRecord(hx.e_ctx, hx.s1);
  cudaStreamWaitEvent(s0, hx.e_ctx, 0);
  k_epi<<<2048, 256, 0, s0>>>(nxy, spa, ang, wnet_w, wnet_b, cnet_w, cnet_b, out);

  // fork: vref ictx-chunks (z=1..20) depend only on epi; run beside psv
  cudaEventRecord(hx.e_epi, s0);
  cudaStreamWaitEvent(hx.s1, hx.e_epi, 0);
  k_vref<<<dim3(16, 20), 256, 0, hx.s1>>>(vref_w, vref_b, out, 0);

  // psv (computes blended inline) then remaining vref chunks on s0
  k_psv <<<dim3(16, 2, 4), 256, 0, s0>>>(psvs, psv_w, psv_b, out);
  k_vref<<<dim3(16, 23), 256, 0, s0>>>(vref_w, vref_b, out, 1);

  // join: vfin needs all 43 partials
  cudaEventRecord(hx.e_vA, hx.s1);
  cudaStreamWaitEvent(s0, hx.e_vA, 0);
  k_vfin<<<96, 128, 0, s0>>>(out);
}

// round 14
// speedup vs baseline: 1.0831x; 1.0831x over previous
#include <cuda_runtime.h>

#define NS   4
#define NP   4096      // 64*64 pixels
#define NSZ  24
#define CN   64

// Output layout (flat concat of the 5-tuple, f32)
#define OFF_R0 0
#define OFF_BL 12288
#define OFF_IV 24576
#define OFF_WT 73728
#define OFF_CF 466944

#define VCHUNK 12
#define NVCH   43      // ceil(515/12)

// 4-row chunks: tile = 6 rows x 66 cols per channel
#define TW   66
#define TS4  396

// Scratch
__device__ float  g_ceT [NS*NP*CN];     // flow features, pixel-major [s][p][c]
__device__ float  g_ctxT[NS*NP*CN];     // ctx features,  pixel-major
__device__ float4 g_rec [NS*NP];        // {dotW(ce 0..31), dotC, sv0, sv1}
__device__ float4 g_rec2[NS*NP];        // {dotW(ce 32..63 + sf), dotC, sv2, 0}
__device__ float  g_ictx[NS*CN*NP];     // interp_ctx, channel-major
__device__ float  g_psv [NS*CN*NP];     // psv_feat,   channel-major
__device__ float  g_vpart[NVCH*3*NP];

__device__ __forceinline__ float wsum(float v){
  #pragma unroll
  for (int o = 16; o; o >>= 1) v += __shfl_xor_sync(0xFFFFFFFFu, v, o);
  return v;
}
__device__ __forceinline__ float wmax(float v){
  #pragma unroll
  for (int o = 16; o; o >>= 1) v = fmaxf(v, __shfl_xor_sync(0xFFFFFFFFu, v, o));
  return v;
}

__device__ __forceinline__ void fma16(float acc[16], const float* wbase, float v){
  const float4* w4 = (const float4*)wbase;
  float4 a = w4[0], b = w4[1], c = w4[2], d = w4[3];
  acc[0]=fmaf(a.x,v,acc[0]);   acc[1]=fmaf(a.y,v,acc[1]);
  acc[2]=fmaf(a.z,v,acc[2]);   acc[3]=fmaf(a.w,v,acc[3]);
  acc[4]=fmaf(b.x,v,acc[4]);   acc[5]=fmaf(b.y,v,acc[5]);
  acc[6]=fmaf(b.z,v,acc[6]);   acc[7]=fmaf(b.w,v,acc[7]);
  acc[8]=fmaf(c.x,v,acc[8]);   acc[9]=fmaf(c.y,v,acc[9]);
  acc[10]=fmaf(c.z,v,acc[10]); acc[11]=fmaf(c.w,v,acc[11]);
  acc[12]=fmaf(d.x,v,acc[12]); acc[13]=fmaf(d.y,v,acc[13]);
  acc[14]=fmaf(d.z,v,acc[14]); acc[15]=fmaf(d.w,v,acc[15]);
}

// ---------------------------------------------------------------------------
// K1: flowRefNet conv 18->64, relu, pixel-major + per-pixel dot records.
// grid (16 rowchunks of 4, 2 oc-halves, 4 src), block 256 (4 rows x 64 cols)
// ---------------------------------------------------------------------------
__global__ void __launch_bounds__(256) k_flow(
    const float* __restrict__ sf, const float* __restrict__ sv,
    const float* __restrict__ wv,
    const float* __restrict__ fw, const float* __restrict__ fb,
    const float* __restrict__ ww, const float* __restrict__ cw){
  __shared__ float s_in[18*TS4];
  __shared__ __align__(16) float buf[4352];
  __shared__ float s_wc[140];
  int rc = blockIdx.x, half = blockIdx.y, bs = blockIdx.z;
  int tid = threadIdx.x, r0 = rc*4;

  for (int i = tid; i < 18*TS4; i += 256){
    int c = i/TS4, rem = i - c*TS4, ry = rem/TW, rx = rem - ry*TW;
    int gy = r0 - 1 + ry, gx = rx - 1;
    float v = 0.f;
    if ((unsigned)gy < 64u && (unsigned)gx < 64u){
      const float* src = (c < 6) ? sf + (bs*6 + c)*NP
                       : (c < 9) ? sv + (bs*3 + (c-6))*NP
                                 : wv + (bs*9 + (c-9))*NP;
      v = src[gy*64 + gx];
    }
    s_in[i] = v;
  }
  for (int i = tid; i < 140; i += 256) s_wc[i] = (i < 70) ? ww[i] : cw[i-70];
  __syncthreads();

  int ly = tid >> 6, lx = tid & 63;
  int p = (r0 + ly)*64 + lx;
  int tl = ly*TW + lx;
  float dW = 0.f, dC = 0.f;

  #pragma unroll 1
  for (int sub = 0; sub < 2; sub++){
    int oc0 = half*32 + sub*16;
    for (int i = tid; i < 2592; i += 256){
      int j = i & 15, ct = i >> 4;
      buf[i] = fw[(oc0 + j)*162 + ct];
    }
    __syncthreads();
    float acc[16];
    #pragma unroll
    for (int j = 0; j < 16; j++) acc[j] = fb[oc0 + j];
    #pragma unroll 1
    for (int c = 0; c < 18; c++){
      const float* cin = s_in + c*TS4 + tl;
      float v[9];
      #pragma unroll
      for (int ky = 0; ky < 3; ky++)
        #pragma unroll
        for (int kx = 0; kx < 3; kx++) v[ky*3+kx] = cin[ky*TW + kx];
      #pragma unroll
      for (int t = 0; t < 9; t++) fma16(acc, buf + (c*9 + t)*16, v[t]);
    }
    __syncthreads();
    #pragma unroll
    for (int j = 0; j < 16; j++){
      float r = fmaxf(acc[j], 0.f);
      dW = fmaf(s_wc[6 + oc0 + j],  r, dW);
      dC = fmaf(s_wc[76 + oc0 + j], r, dC);
      buf[tid*17 + j] = r;
    }
    __syncthreads();
    for (int i = tid; i < 4096; i += 256){
      int pl = i >> 4, j = i & 15;
      g_ceT[(bs*NP + r0*64 + pl)*64 + oc0 + j] = buf[pl*17 + j];
    }
    __syncthreads();
  }

  int cofs = (ly+1)*TW + (lx+1);
  if (half == 0){
    g_rec[bs*NP + p] = make_float4(dW, dC, s_in[6*TS4 + cofs], s_in[7*TS4 + cofs]);
  } else {
    #pragma unroll
    for (int j = 0; j < 6; j++){
      float t = s_in[j*TS4 + cofs];
      dW = fmaf(s_wc[j],      t, dW);
      dC = fmaf(s_wc[70 + j], t, dC);
    }
    g_rec2[bs*NP + p] = make_float4(dW, dC, s_in[8*TS4 + cofs], 0.f);
  }
}

// ---------------------------------------------------------------------------
// K1b: ctxNet conv 3->64, relu, pixel-major. grid (16,2,4), block 256.
// Runs concurrently with k_flow on a side stream.
// ---------------------------------------------------------------------------
__global__ void __launch_bounds__(256) k_ctx(
    const float* __restrict__ sv, const float* __restrict__ cxw,
    const float* __restrict__ cxb){
  __shared__ float s_in[3*TS4];
  __shared__ __align__(16) float s_w[27*32];
  __shared__ float s_out[256*33];
  int rc = blockIdx.x, half = blockIdx.y, bs = blockIdx.z;
  int tid = threadIdx.x, r0 = rc*4;
  int oc0 = half*32;

  for (int i = tid; i < 3*TS4; i += 256){
    int c = i/TS4, rem = i - c*TS4, ry = rem/TW, rx = rem - ry*TW;
    int gy = r0 - 1 + ry, gx = rx - 1;
    s_in[i] = ((unsigned)gy < 64u && (unsigned)gx < 64u)
              ? sv[(bs*3 + c)*NP + gy*64 + gx] : 0.f;
  }
  for (int i = tid; i < 864; i += 256){
    int j = i & 31, ct = i >> 5;
    s_w[ct*32 + j] = cxw[(oc0 + j)*27 + ct];
  }
  __syncthreads();

  int ly = tid >> 6, lx = tid & 63;
  int tl = ly*TW + lx;
  float acc[32];
  #pragma unroll
  for (int j = 0; j < 32; j++) acc[j] = cxb[oc0 + j];
  #pragma unroll
  for (int c = 0; c < 3; c++){
    const float* cin = s_in + c*TS4 + tl;
    float v[9];
    #pragma unroll
    for (int ky = 0; ky < 3; ky++)
      #pragma unroll
      for (int kx = 0; kx < 3; kx++) v[ky*3+kx] = cin[ky*TW + kx];
    #pragma unroll
    for (int t = 0; t < 9; t++){
      fma16(acc,      s_w + (c*9 + t)*32,      v[t]);
      fma16(acc + 16, s_w + (c*9 + t)*32 + 16, v[t]);
    }
  }
  #pragma unroll
  for (int j = 0; j < 32; j++) s_out[tid*33 + j] = fmaxf(acc[j], 0.f);
  __syncthreads();
  for (int i = tid; i < 8192; i += 256){
    int pl = i >> 5, j = i & 31;
    g_ctxT[(bs*NP + r0*64 + pl)*64 + oc0 + j] = s_out[pl*33 + j];
  }
}

// ---------------------------------------------------------------------------
// K2: fused epipolar gather + logits + softmax + interps + conf blend.
// Block = 8 pixels x 4 sources (32 warps, 1024 threads); warp = (pixel,src).
// In-block conf softmax + blend after all 4 sources of a pixel finish.
// grid 512, block 1024.
// ---------------------------------------------------------------------------
__global__ void __launch_bounds__(1024) k_epi(
    const int* __restrict__ nxy,
    const float* __restrict__ spa, const float* __restrict__ ang,
    const float* __restrict__ ww,  const float* __restrict__ wb,
    const float* __restrict__ cw,  const float* __restrict__ cb,
    float* __restrict__ out){
  __shared__ float s_ww[206], s_cw[206];
  __shared__ float s_sa[4*8*216];       // [src][px][n*9 + j]
  __shared__ float s_cl[8][4];          // conf logits per (px, src)
  __shared__ float s_iv[8][4][3];       // interp_view per (px, src)
  int tid = threadIdx.x;
  for (int i = tid; i < 206; i += 1024){ s_ww[i] = ww[i]; s_cw[i] = cw[i]; }

  int p0 = blockIdx.x*8;

  // stage spa/ang for all 4 sources x 8 pixels (coalesced over pixels)
  for (int i = tid; i < 6144; i += 1024){
    int pp = i & 7;
    int n  = (i >> 3) % 24;
    int t  = i / 192;                   // 0..31
    int bs = t >> 3, j = t & 7;
    const float* src = (j < 2) ? spa + ((bs*2 + j)*NSZ + n)*NP
                               : ang + ((bs*6 + (j-2))*NSZ + n)*NP;
    s_sa[(bs*8 + pp)*216 + n*9 + j] = src[p0 + pp];
  }
  __syncthreads();

  int warp = tid >> 5, lane = tid & 31;
  int pp = warp >> 2, bs = warp & 3;
  int p = p0 + pp;
  bool act = lane < NSZ;
  const float* mysa = s_sa + (bs*8 + pp)*216;

  int idx = 0;
  if (act){
    int e = lane / 3, k = lane % 3;
    const int* q = nxy + ((bs*NP + p)*8 + e)*2;
    int xi = min(max(q[0], 0), 63);
    int yi = min(max(q[1] + (k - 1), 0), 63);
    idx = yi*64 + xi;
  }

  float mylogit = 0.f, myclog = 0.f, sv0 = 0.f, sv1 = 0.f, sv2 = 0.f;
  if (act){
    float4 A = g_rec [bs*NP + idx];
    float4 B = g_rec2[bs*NP + idx];
    mylogit = A.x + B.x;  myclog = A.y + B.y;
    sv0 = A.z; sv1 = A.w; sv2 = B.z;
    #pragma unroll
    for (int j = 0; j < 8; j++){
      float t = mysa[lane*9 + j];
      mylogit = fmaf(s_ww[198 + j], t, mylogit);
      myclog  = fmaf(s_cw[198 + j], t, myclog);
    }
  }

  const float* ceT = g_ceT + (size_t)bs*NP*CN;
  float a0 = 0.f, a1 = 0.f, sq0 = 0.f, sq1 = 0.f;
  #pragma unroll 4
  for (int n = 0; n < NSZ; n++){
    int ix = __shfl_sync(0xFFFFFFFFu, idx, n);
    float u0 = ceT[ix*CN + lane];
    float u1 = ceT[ix*CN + 32 + lane];
    a0 += u0; sq0 = fmaf(u0, u0, sq0);
    a1 += u1; sq1 = fmaf(u1, u1, sq1);
  }
  float mu0 = a0*(1.f/24.f), mu1 = a1*(1.f/24.f);
  float vr0 = (sq0 - 24.f*mu0*mu0)*(1.f/23.f);
  float vr1 = (sq1 - 24.f*mu1*mu1)*(1.f/23.f);
  float mw = s_ww[70+lane]*mu0 + s_ww[102+lane]*mu1 + s_ww[134+lane]*vr0 + s_ww[166+lane]*vr1;
  float mc = s_cw[70+lane]*mu0 + s_cw[102+lane]*mu1 + s_cw[134+lane]*vr0 + s_cw[166+lane]*vr1;
  mw = wsum(mw); mc = wsum(mc);
  mylogit += mw + wb[0];
  myclog  += mc + cb[0];

  float m  = wmax(act ? mylogit : -1e30f);
  float e  = act ? __expf(mylogit - m) : 0.f;
  float se = wsum(e);
  float wgt = e / se;
  if (act) out[OFF_WT + (bs*NP + p)*NSZ + lane] = wgt;

  float cs = wsum(act ? wgt*myclog : 0.f);

  float r0 = wsum(act ? wgt*sv0 : 0.f);
  float r1 = wsum(act ? wgt*sv1 : 0.f);
  float r2 = wsum(act ? wgt*sv2 : 0.f);
  if (lane == 0){
    out[OFF_IV + (bs*3 + 0)*NP + p] = r0;
    out[OFF_IV + (bs*3 + 1)*NP + p] = r1;
    out[OFF_IV + (bs*3 + 2)*NP + p] = r2;
    s_cl[pp][bs] = cs;
    s_iv[pp][bs][0] = r0; s_iv[pp][bs][1] = r1; s_iv[pp][bs][2] = r2;
  }

  // interp_ctx pass
  const float* ctxT = g_ctxT + (size_t)bs*NP*CN;
  float acc0 = 0.f, acc1 = 0.f;
  #pragma unroll 4
  for (int n = 0; n < NSZ; n++){
    int ix = __shfl_sync(0xFFFFFFFFu, idx, n);
    float wn = __shfl_sync(0xFFFFFFFFu, wgt, n);
    acc0 = fmaf(wn, ctxT[ix*CN + lane], acc0);
    acc1 = fmaf(wn, ctxT[ix*CN + 32 + lane], acc1);
  }
  g_ictx[(bs*CN + lane)*NP + p]      = acc0;
  g_ictx[(bs*CN + 32 + lane)*NP + p] = acc1;

  // in-block conf softmax + blend (one thread per pixel)
  __syncthreads();
  if (tid < 8){
    int q = p0 + tid;
    float c0 = s_cl[tid][0], c1 = s_cl[tid][1];
    float c2 = s_cl[tid][2], c3 = s_cl[tid][3];
    float mm = fmaxf(fmaxf(c0, c1), fmaxf(c2, c3));
    float e0 = __expf(c0 - mm), e1 = __expf(c1 - mm);
    float e2 = __expf(c2 - mm), e3 = __expf(c3 - mm);
    float inv = 1.f/(e0 + e1 + e2 + e3);
    float f0 = e0*inv, f1 = e1*inv, f2 = e2*inv, f3 = e3*inv;
    out[OFF_CF + q]        = f0;
    out[OFF_CF + NP + q]   = f1;
    out[OFF_CF + 2*NP + q] = f2;
    out[OFF_CF + 3*NP + q] = f3;
    #pragma unroll
    for (int c = 0; c < 3; c++){
      float bl = f0*s_iv[tid][0][c] + f1*s_iv[tid][1][c]
               + f2*s_iv[tid][2][c] + f3*s_iv[tid][3][c];
      out[OFF_BL + c*NP + q] = bl;
    }
  }
}

// ---------------------------------------------------------------------------
// K4: psvNet conv 6->64 per depth, relu, mean over D=8. grid (16,2,4), 256.
// ---------------------------------------------------------------------------
__global__ void __launch_bounds__(256) k_psv(
    const float* __restrict__ psvs, const float* __restrict__ pw,
    const float* __restrict__ pb, const float* __restrict__ out){
  __shared__ float s_bl[3*TS4];
  __shared__ float s_ps[24*TS4];
  __shared__ __align__(16) float s_w[864];
  int rc = blockIdx.x, half = blockIdx.y, bs = blockIdx.z;
  int tid = threadIdx.x, r0 = rc*4;

  for (int i = tid; i < 3*TS4; i += 256){
    int c = i/TS4, rem = i - c*TS4, ry = rem/TW, rx = rem - ry*TW;
    int gy = r0 - 1 + ry, gx = rx - 1;
    s_bl[i] = ((unsigned)gy < 64u && (unsigned)gx < 64u)
              ? out[OFF_BL + c*NP + gy*64 + gx] : 0.f;
  }
  for (int i = tid; i < 24*TS4; i += 256){
    int cd = i/TS4, rem = i - cd*TS4, ry = rem/TW, rx = rem - ry*TW;
    int c = cd >> 3, d = cd & 7;
    int gy = r0 - 1 + ry, gx = rx - 1;
    s_ps[i] = ((unsigned)gy < 64u && (unsigned)gx < 64u)
              ? psvs[(((bs*3 + c)*8) + d)*NP + gy*64 + gx] : 0.f;
  }

  int ly = tid >> 6, lx = tid & 63;
  int p = (r0 + ly)*64 + lx;
  int tl = ly*TW + lx;

  #pragma unroll 1
  for (int sub = 0; sub < 2; sub++){
    int oc0 = half*32 + sub*16;
    if (sub) __syncthreads();
    for (int i = tid; i < 864; i += 256){
      int j = i & 15, ct = i >> 4;
      s_w[i] = pw[(oc0 + j)*54 + ct];
    }
    __syncthreads();

    float blp[16];
    #pragma unroll
    for (int j = 0; j < 16; j++) blp[j] = pb[oc0 + j];
    #pragma unroll
    for (int c = 0; c < 3; c++){
      const float* cin = s_bl + c*TS4 + tl;
      float v[9];
      #pragma unroll
      for (int ky = 0; ky < 3; ky++)
        #pragma unroll
        for (int kx = 0; kx < 3; kx++) v[ky*3+kx] = cin[ky*TW + kx];
      #pragma unroll
      for (int t = 0; t < 9; t++) fma16(blp, s_w + ((3 + c)*9 + t)*16, v[t]);
    }
    float oacc[16];
    #pragma unroll
    for (int j = 0; j < 16; j++) oacc[j] = 0.f;
    #pragma unroll 1
    for (int d = 0; d < 8; d++){
      float pv[16];
      #pragma unroll
      for (int j = 0; j < 16; j++) pv[j] = blp[j];
      #pragma unroll
      for (int c = 0; c < 3; c++){
        const float* cin = s_ps + (c*8 + d)*TS4 + tl;
        float v[9];
        #pragma unroll
        for (int ky = 0; ky < 3; ky++)
          #pragma unroll
          for (int kx = 0; kx < 3; kx++) v[ky*3+kx] = cin[ky*TW + kx];
        #pragma unroll
        for (int t = 0; t < 9; t++) fma16(pv, s_w + (c*9 + t)*16, v[t]);
      }
      #pragma unroll
      for (int j = 0; j < 16; j++) oacc[j] += fmaxf(pv[j], 0.f);
    }
    #pragma unroll
    for (int j = 0; j < 16; j++)
      g_psv[(bs*CN + oc0 + j)*NP + p] = oacc[j] * 0.125f;
  }
}

// ---------------------------------------------------------------------------
// K5: vref conv 515->3, ic-chunked (12). mode 0: z=1+by (ictx-only chunks,
// depends only on k_epi). mode 1: z=0 or 20+by (blended/psv chunks).
// grid (16, 20|23), block 256.
// ---------------------------------------------------------------------------
__global__ void __launch_bounds__(256) k_vref(
    const float* __restrict__ vw, const float* __restrict__ vb,
    const float* __restrict__ out, int mode){
  __shared__ float s_in[VCHUNK*TS4];
  __shared__ __align__(16) float s_w[VCHUNK*9*4];
  int rc = blockIdx.x;
  int z = (mode == 0) ? (1 + blockIdx.y)
                      : ((blockIdx.y == 0) ? 0 : 20 + blockIdx.y);
  int tid = threadIdx.x, r0 = rc*4;
  int ic0 = z*VCHUNK;
  int nch = min(VCHUNK, 515 - ic0);

  for (int i = tid; i < nch*TS4; i += 256){
    int c = i/TS4, rem = i - c*TS4, ry = rem/TW, rx = rem - ry*TW;
    int ic = ic0 + c;
    int gy = r0 - 1 + ry, gx = rx - 1;
    float v = 0.f;
    if ((unsigned)gy < 64u && (unsigned)gx < 64u){
      const float* src = (ic < 3)   ? out + OFF_BL + ic*NP
                       : (ic < 259) ? g_ictx + (ic - 3)*NP
                                    : g_psv  + (ic - 259)*NP;
      v = src[gy*64 + gx];
    }
    s_in[i] = v;
  }
  for (int i = tid; i < nch*9*4; i += 256){
    int oc = i & 3, ct = i >> 2;
    s_w[i] = (oc < 3) ? vw[(oc*515 + ic0)*9 + ct] : 0.f;
  }
  __syncthreads();

  int ly = tid >> 6, lx = tid & 63;
  int p = (r0 + ly)*64 + lx;
  int tl = ly*TW + lx;
  float acc0 = (z == 0) ? vb[0] : 0.f;
  float acc1 = (z == 0) ? vb[1] : 0.f;
  float acc2 = (z == 0) ? vb[2] : 0.f;
  #pragma unroll 1
  for (int c = 0; c < nch; c++){
    const float* cin = s_in + c*TS4 + tl;
    float v[9];
    #pragma unroll
    for (int ky = 0; ky < 3; ky++)
      #pragma unroll
      for (int kx = 0; kx < 3; kx++) v[ky*3+kx] = cin[ky*TW + kx];
    #pragma unroll
    for (int t = 0; t < 9; t++){
      float4 w = *(const float4*)(s_w + (c*9 + t)*4);
      acc0 = fmaf(w.x, v[t], acc0);
      acc1 = fmaf(w.y, v[t], acc1);
      acc2 = fmaf(w.z, v[t], acc2);
    }
  }
  g_vpart[(z*3 + 0)*NP + p] = acc0;
  g_vpart[(z*3 + 1)*NP + p] = acc1;
  g_vpart[(z*3 + 2)*NP + p] = acc2;
}

__global__ void __launch_bounds__(128) k_vfin(float* __restrict__ out){
  int i = blockIdx.x*128 + threadIdx.x;   // 0..12287
  float a = 0.f;
  #pragma unroll
  for (int z = 0; z < NVCH; z++) a += g_vpart[z*3*NP + i];
  out[OFF_R0 + i] = a;
}

// ---------------------------------------------------------------------------
// Side stream + events, created at static init.
// ---------------------------------------------------------------------------
struct HxAsync {
  cudaStream_t s1;
  cudaEvent_t e_root, e_ctx, e_epi, e_vA;
  HxAsync(){
    cudaStreamCreateWithFlags(&s1, cudaStreamNonBlocking);
    cudaEventCreateWithFlags(&e_root, cudaEventDisableTiming);
    cudaEventCreateWithFlags(&e_ctx,  cudaEventDisableTiming);
    cudaEventCreateWithFlags(&e_epi,  cudaEventDisableTiming);
    cudaEventCreateWithFlags(&e_vA,   cudaEventDisableTiming);
  }
};
static HxAsync hx;

// ---------------------------------------------------------------------------
extern "C" void kernel_launch(void* const* d_in, const int* in_sizes, int n_in,
                              void* d_out, int out_size){
  const float* sv   = (const float*)d_in[0];
  const float* sf   = (const float*)d_in[1];
  const float* psvs = (const float*)d_in[2];
  const float* wv   = (const float*)d_in[3];
  const int*   nxy  = (const int*)  d_in[5];
  const float* spa  = (const float*)d_in[6];
  const float* ang  = (const float*)d_in[7];
  const float* flow_w = (const float*)d_in[9];
  const float* flow_b = (const float*)d_in[10];
  const float* ctx_w  = (const float*)d_in[11];
  const float* ctx_b  = (const float*)d_in[12];
  const float* wnet_w = (const float*)d_in[13];
  const float* wnet_b = (const float*)d_in[14];
  const float* cnet_w = (const float*)d_in[15];
  const float* cnet_b = (const float*)d_in[16];
  const float* psv_w  = (const float*)d_in[17];
  const float* psv_b  = (const float*)d_in[18];
  const float* vref_w = (const float*)d_in[19];
  const float* vref_b = (const float*)d_in[20];
  float* out = (float*)d_out;
  cudaStream_t s0 = (cudaStream_t)0;

  // fork: ctx runs concurrently with flow on side stream
  cudaEventRecord(hx.e_root, s0);
  cudaStreamWaitEvent(hx.s1, hx.e_root, 0);

  k_flow<<<dim3(16, 2, 4), 256, 0, s0>>>(sf, sv, wv, flow_w, flow_b,
                                         wnet_w, cnet_w);
  k_ctx <<<dim3(16, 2, 4), 256, 0, hx.s1>>>(sv, ctx_w, ctx_b);

  // join: epi needs both flow (s0 order) and ctx
  cudaEventRecord(hx.e_ctx, hx.s1);
  cudaStreamWaitEvent(s0, hx.e_ctx, 0);
  k_epi<<<512, 1024, 0, s0>>>(nxy, spa, ang, wnet_w, wnet_b, cnet_w, cnet_b, out);

  // fork: vref ictx-chunks (z=1..20) depend only on epi; run beside psv
  cudaEventRecord(hx.e_epi, s0);
  cudaStreamWaitEvent(hx.s1, hx.e_epi, 0);
  k_vref<<<dim3(16, 20), 256, 0, hx.s1>>>(vref_w, vref_b, out, 0);

  // psv then remaining vref chunks on s0 (blended already written by epi)
  k_psv <<<dim3(16, 2, 4), 256, 0, s0>>>(psvs, psv_w, psv_b, out);
  k_vref<<<dim3(16, 23), 256, 0, s0>>>(vref_w, vref_b, out, 1);

  // join: vfin needs all 43 partials
  cudaEventRecord(hx.e_vA, hx.s1);
  cudaStreamWaitEvent(s0, hx.e_vA, 0);
  k_vfin<<<96, 128, 0, s0>>>(out);
}

// round 17
// speedup vs baseline: 1.1230x; 1.0368x over previous
#include <cuda_runtime.h>

#define NS   4
#define NP   4096      // 64*64 pixels
#define NSZ  24
#define CN   64

// Output layout (flat concat of the 5-tuple, f32)
#define OFF_R0 0
#define OFF_BL 12288
#define OFF_IV 24576
#define OFF_WT 73728
#define OFF_CF 466944

#define VCHUNK 12
#define NVCH   43      // ceil(515/12)

// 4-row chunks: tile = 6 rows x 66 cols per channel
#define TW   66
#define TS4  396

// Scratch
__device__ float  g_ceT [NS*NP*CN];     // flow features, pixel-major [s][p][c]
__device__ float  g_ctxT[NS*NP*CN];     // ctx features,  pixel-major
__device__ float4 g_rec [NS*NP];        // {dotW(ce 0..31), dotC, sv0, sv1}
__device__ float4 g_rec2[NS*NP];        // {dotW(ce 32..63 + sf), dotC, sv2, 0}
__device__ float  g_ictx[NS*CN*NP];     // interp_ctx, channel-major
__device__ float  g_psv [NS*CN*NP];     // psv_feat,   channel-major
__device__ float  g_clog[NS*NP];
__device__ float  g_vpart[NVCH*3*NP];

__device__ __forceinline__ float wsum(float v){
  #pragma unroll
  for (int o = 16; o; o >>= 1) v += __shfl_xor_sync(0xFFFFFFFFu, v, o);
  return v;
}
__device__ __forceinline__ float wmax(float v){
  #pragma unroll
  for (int o = 16; o; o >>= 1) v = fmaxf(v, __shfl_xor_sync(0xFFFFFFFFu, v, o));
  return v;
}

__device__ __forceinline__ void fma16(float acc[16], const float* wbase, float v){
  const float4* w4 = (const float4*)wbase;
  float4 a = w4[0], b = w4[1], c = w4[2], d = w4[3];
  acc[0]=fmaf(a.x,v,acc[0]);   acc[1]=fmaf(a.y,v,acc[1]);
  acc[2]=fmaf(a.z,v,acc[2]);   acc[3]=fmaf(a.w,v,acc[3]);
  acc[4]=fmaf(b.x,v,acc[4]);   acc[5]=fmaf(b.y,v,acc[5]);
  acc[6]=fmaf(b.z,v,acc[6]);   acc[7]=fmaf(b.w,v,acc[7]);
  acc[8]=fmaf(c.x,v,acc[8]);   acc[9]=fmaf(c.y,v,acc[9]);
  acc[10]=fmaf(c.z,v,acc[10]); acc[11]=fmaf(c.w,v,acc[11]);
  acc[12]=fmaf(d.x,v,acc[12]); acc[13]=fmaf(d.y,v,acc[13]);
  acc[14]=fmaf(d.z,v,acc[14]); acc[15]=fmaf(d.w,v,acc[15]);
}

// ---------------------------------------------------------------------------
// K1: flowRefNet conv 18->64, relu, pixel-major + per-pixel dot records.
// grid (16 rowchunks of 4, 2 oc-halves, 4 src), block 256.
// Both 16-oc weight subs preloaded; direct float4 stores; ONE barrier total.
// ---------------------------------------------------------------------------
__global__ void __launch_bounds__(256) k_flow(
    const float* __restrict__ sf, const float* __restrict__ sv,
    const float* __restrict__ wv,
    const float* __restrict__ fw, const float* __restrict__ fb,
    const float* __restrict__ ww, const float* __restrict__ cw){
  __shared__ float s_in[18*TS4];                 // 28.5 KB
  __shared__ __align__(16) float s_fw[2*2592];   // both subs, tap-major, 20.7 KB
  __shared__ float s_wc[140];
  int rc = blockIdx.x, half = blockIdx.y, bs = blockIdx.z;
  int tid = threadIdx.x, r0 = rc*4;

  for (int i = tid; i < 18*TS4; i += 256){
    int c = i/TS4, rem = i - c*TS4, ry = rem/TW, rx = rem - ry*TW;
    int gy = r0 - 1 + ry, gx = rx - 1;
    float v = 0.f;
    if ((unsigned)gy < 64u && (unsigned)gx < 64u){
      const float* src = (c < 6) ? sf + (bs*6 + c)*NP
                       : (c < 9) ? sv + (bs*3 + (c-6))*NP
                                 : wv + (bs*9 + (c-9))*NP;
      v = src[gy*64 + gx];
    }
    s_in[i] = v;
  }
  for (int i = tid; i < 140; i += 256) s_wc[i] = (i < 70) ? ww[i] : cw[i-70];
  for (int i = tid; i < 2*2592; i += 256){
    int sub = i / 2592, rem = i - sub*2592;
    int j = rem & 15, ct = rem >> 4;
    s_fw[i] = fw[(half*32 + sub*16 + j)*162 + ct];
  }
  __syncthreads();

  int ly = tid >> 6, lx = tid & 63;
  int p = (r0 + ly)*64 + lx;
  int tl = ly*TW + lx;
  float dW = 0.f, dC = 0.f;

  #pragma unroll 1
  for (int sub = 0; sub < 2; sub++){
    int oc0 = half*32 + sub*16;
    const float* wsub = s_fw + sub*2592;
    float acc[16];
    #pragma unroll
    for (int j = 0; j < 16; j++) acc[j] = fb[oc0 + j];
    #pragma unroll 1
    for (int c = 0; c < 18; c++){
      const float* cin = s_in + c*TS4 + tl;
      float v[9];
      #pragma unroll
      for (int ky = 0; ky < 3; ky++)
        #pragma unroll
        for (int kx = 0; kx < 3; kx++) v[ky*3+kx] = cin[ky*TW + kx];
      #pragma unroll
      for (int t = 0; t < 9; t++) fma16(acc, wsub + (c*9 + t)*16, v[t]);
    }
    float4 o[4];
    #pragma unroll
    for (int q = 0; q < 4; q++){
      float r0v = fmaxf(acc[q*4 + 0], 0.f);
      float r1v = fmaxf(acc[q*4 + 1], 0.f);
      float r2v = fmaxf(acc[q*4 + 2], 0.f);
      float r3v = fmaxf(acc[q*4 + 3], 0.f);
      dW = fmaf(s_wc[6 + oc0 + q*4 + 0], r0v, dW);
      dW = fmaf(s_wc[6 + oc0 + q*4 + 1], r1v, dW);
      dW = fmaf(s_wc[6 + oc0 + q*4 + 2], r2v, dW);
      dW = fmaf(s_wc[6 + oc0 + q*4 + 3], r3v, dW);
      dC = fmaf(s_wc[76 + oc0 + q*4 + 0], r0v, dC);
      dC = fmaf(s_wc[76 + oc0 + q*4 + 1], r1v, dC);
      dC = fmaf(s_wc[76 + oc0 + q*4 + 2], r2v, dC);
      dC = fmaf(s_wc[76 + oc0 + q*4 + 3], r3v, dC);
      o[q] = make_float4(r0v, r1v, r2v, r3v);
    }
    float4* dst = (float4*)(g_ceT + (size_t)(bs*NP + p)*CN + oc0);
    dst[0] = o[0]; dst[1] = o[1]; dst[2] = o[2]; dst[3] = o[3];
  }

  // per-pixel record epilogue
  int cofs = (ly+1)*TW + (lx+1);
  if (half == 0){
    g_rec[bs*NP + p] = make_float4(dW, dC, s_in[6*TS4 + cofs], s_in[7*TS4 + cofs]);
  } else {
    #pragma unroll
    for (int j = 0; j < 6; j++){
      float t = s_in[j*TS4 + cofs];
      dW = fmaf(s_wc[j],      t, dW);
      dC = fmaf(s_wc[70 + j], t, dC);
    }
    g_rec2[bs*NP + p] = make_float4(dW, dC, s_in[8*TS4 + cofs], 0.f);
  }
}

// ---------------------------------------------------------------------------
// K1b: ctxNet conv 3->64, relu, pixel-major. grid (16,2,4), block 256.
// Runs concurrently with k_flow on a side stream.
// ---------------------------------------------------------------------------
__global__ void __launch_bounds__(256) k_ctx(
    const float* __restrict__ sv, const float* __restrict__ cxw,
    const float* __restrict__ cxb){
  __shared__ float s_in[3*TS4];
  __shared__ __align__(16) float s_w[27*32];
  __shared__ float s_out[256*33];
  int rc = blockIdx.x, half = blockIdx.y, bs = blockIdx.z;
  int tid = threadIdx.x, r0 = rc*4;
  int oc0 = half*32;

  for (int i = tid; i < 3*TS4; i += 256){
    int c = i/TS4, rem = i - c*TS4, ry = rem/TW, rx = rem - ry*TW;
    int gy = r0 - 1 + ry, gx = rx - 1;
    s_in[i] = ((unsigned)gy < 64u && (unsigned)gx < 64u)
              ? sv[(bs*3 + c)*NP + gy*64 + gx] : 0.f;
  }
  for (int i = tid; i < 864; i += 256){
    int j = i & 31, ct = i >> 5;
    s_w[ct*32 + j] = cxw[(oc0 + j)*27 + ct];
  }
  __syncthreads();

  int ly = tid >> 6, lx = tid & 63;
  int tl = ly*TW + lx;
  float acc[32];
  #pragma unroll
  for (int j = 0; j < 32; j++) acc[j] = cxb[oc0 + j];
  #pragma unroll
  for (int c = 0; c < 3; c++){
    const float* cin = s_in + c*TS4 + tl;
    float v[9];
    #pragma unroll
    for (int ky = 0; ky < 3; ky++)
      #pragma unroll
      for (int kx = 0; kx < 3; kx++) v[ky*3+kx] = cin[ky*TW + kx];
    #pragma unroll
    for (int t = 0; t < 9; t++){
      fma16(acc,      s_w + (c*9 + t)*32,      v[t]);
      fma16(acc + 16, s_w + (c*9 + t)*32 + 16, v[t]);
    }
  }
  #pragma unroll
  for (int j = 0; j < 32; j++) s_out[tid*33 + j] = fmaxf(acc[j], 0.f);
  __syncthreads();
  for (int i = tid; i < 8192; i += 256){
    int pl = i >> 5, j = i & 31;
    g_ctxT[(bs*NP + r0*64 + pl)*64 + oc0 + j] = s_out[pl*33 + j];
  }
}

// ---------------------------------------------------------------------------
// K2: fused epipolar gather + logits + softmax + interps. grid 2048, block 256
// ---------------------------------------------------------------------------
__global__ void __launch_bounds__(256) k_epi(
    const int* __restrict__ nxy,
    const float* __restrict__ spa, const float* __restrict__ ang,
    const float* __restrict__ ww,  const float* __restrict__ wb,
    const float* __restrict__ cw,  const float* __restrict__ cb,
    float* __restrict__ out){
  __shared__ float s_ww[206], s_cw[206];
  __shared__ float s_sa[8][NSZ*9];
  int tid = threadIdx.x;
  for (int i = tid; i < 206; i += 256){ s_ww[i] = ww[i]; s_cw[i] = cw[i]; }

  int gp0 = blockIdx.x*8;
  int bs = gp0 >> 12, p0 = gp0 & 4095;

  for (int i = tid; i < 1536; i += 256){
    int pp = i & 7;
    int n  = (i >> 3) % 24;
    int j  = i / 192;
    const float* src = (j < 2) ? spa + ((bs*2 + j)*NSZ + n)*NP
                               : ang + ((bs*6 + (j-2))*NSZ + n)*NP;
    s_sa[pp][n*9 + j] = src[p0 + pp];
  }
  __syncthreads();

  int warp = tid >> 5, lane = tid & 31;
  int p = p0 + warp;
  bool act = lane < NSZ;

  int idx = 0;
  if (act){
    int e = lane / 3, k = lane % 3;
    const int* q = nxy + ((bs*NP + p)*8 + e)*2;
    int xi = min(max(q[0], 0), 63);
    int yi = min(max(q[1] + (k - 1), 0), 63);
    idx = yi*64 + xi;
  }

  float mylogit = 0.f, myclog = 0.f, sv0 = 0.f, sv1 = 0.f, sv2 = 0.f;
  if (act){
    float4 A = g_rec [bs*NP + idx];
    float4 B = g_rec2[bs*NP + idx];
    mylogit = A.x + B.x;  myclog = A.y + B.y;
    sv0 = A.z; sv1 = A.w; sv2 = B.z;
    #pragma unroll
    for (int j = 0; j < 8; j++){
      float t = s_sa[warp][lane*9 + j];
      mylogit = fmaf(s_ww[198 + j], t, mylogit);
      myclog  = fmaf(s_cw[198 + j], t, myclog);
    }
  }

  const float* ceT = g_ceT + (size_t)bs*NP*CN;
  float a0 = 0.f, a1 = 0.f, sq0 = 0.f, sq1 = 0.f;
  #pragma unroll 4
  for (int n = 0; n < NSZ; n++){
    int ix = __shfl_sync(0xFFFFFFFFu, idx, n);
    float u0 = ceT[ix*CN + lane];
    float u1 = ceT[ix*CN + 32 + lane];
    a0 += u0; sq0 = fmaf(u0, u0, sq0);
    a1 += u1; sq1 = fmaf(u1, u1, sq1);
  }
  float mu0 = a0*(1.f/24.f), mu1 = a1*(1.f/24.f);
  float vr0 = (sq0 - 24.f*mu0*mu0)*(1.f/23.f);
  float vr1 = (sq1 - 24.f*mu1*mu1)*(1.f/23.f);
  float mw = s_ww[70+lane]*mu0 + s_ww[102+lane]*mu1 + s_ww[134+lane]*vr0 + s_ww[166+lane]*vr1;
  float mc = s_cw[70+lane]*mu0 + s_cw[102+lane]*mu1 + s_cw[134+lane]*vr0 + s_cw[166+lane]*vr1;
  mw = wsum(mw); mc = wsum(mc);
  mylogit += mw + wb[0];
  myclog  += mc + cb[0];

  float m  = wmax(act ? mylogit : -1e30f);
  float e  = act ? __expf(mylogit - m) : 0.f;
  float se = wsum(e);
  float wgt = e / se;
  if (act) out[OFF_WT + (bs*NP + p)*NSZ + lane] = wgt;

  float cs = wsum(act ? wgt*myclog : 0.f);
  if (lane == 0) g_clog[bs*NP + p] = cs;

  float r0 = wsum(act ? wgt*sv0 : 0.f);
  float r1 = wsum(act ? wgt*sv1 : 0.f);
  float r2 = wsum(act ? wgt*sv2 : 0.f);
  if (lane == 0){
    out[OFF_IV + (bs*3 + 0)*NP + p] = r0;
    out[OFF_IV + (bs*3 + 1)*NP + p] = r1;
    out[OFF_IV + (bs*3 + 2)*NP + p] = r2;
  }

  const float* ctxT = g_ctxT + (size_t)bs*NP*CN;
  float acc0 = 0.f, acc1 = 0.f;
  #pragma unroll 4
  for (int n = 0; n < NSZ; n++){
    int ix = __shfl_sync(0xFFFFFFFFu, idx, n);
    float wn = __shfl_sync(0xFFFFFFFFu, wgt, n);
    acc0 = fmaf(wn, ctxT[ix*CN + lane], acc0);
    acc1 = fmaf(wn, ctxT[ix*CN + 32 + lane], acc1);
  }
  g_ictx[(bs*CN + lane)*NP + p]      = acc0;
  g_ictx[(bs*CN + 32 + lane)*NP + p] = acc1;
}

// ---------------------------------------------------------------------------
// K3: conf softmax over sources + blend.  grid 16, block 256
// ---------------------------------------------------------------------------
__global__ void k_blend(float* __restrict__ out){
  int p = blockIdx.x*blockDim.x + threadIdx.x;
  float cl[NS]; float m = -1e30f;
  #pragma unroll
  for (int s = 0; s < NS; s++){ cl[s] = g_clog[s*NP + p]; m = fmaxf(m, cl[s]); }
  float se = 0.f;
  #pragma unroll
  for (int s = 0; s < NS; s++){ cl[s] = __expf(cl[s] - m); se += cl[s]; }
  float inv = 1.f/se;
  float bl[3] = {0.f, 0.f, 0.f};
  #pragma unroll
  for (int s = 0; s < NS; s++){
    float cf = cl[s]*inv;
    out[OFF_CF + s*NP + p] = cf;
    #pragma unroll
    for (int c = 0; c < 3; c++)
      bl[c] = fmaf(cf, out[OFF_IV + (s*3 + c)*NP + p], bl[c]);
  }
  #pragma unroll
  for (int c = 0; c < 3; c++) out[OFF_BL + c*NP + p] = bl[c];
}

// ---------------------------------------------------------------------------
// K4: psvNet conv 6->64 per depth, relu, mean over D=8. grid (16,2,4), 256.
// Both weight subs preloaded; single barrier.
// ---------------------------------------------------------------------------
__global__ void __launch_bounds__(256) k_psv(
    const float* __restrict__ psvs, const float* __restrict__ pw,
    const float* __restrict__ pb, const float* __restrict__ out){
  __shared__ float s_bl[3*TS4];
  __shared__ float s_ps[24*TS4];
  __shared__ __align__(16) float s_w[2*864];
  int rc = blockIdx.x, half = blockIdx.y, bs = blockIdx.z;
  int tid = threadIdx.x, r0 = rc*4;

  for (int i = tid; i < 3*TS4; i += 256){
    int c = i/TS4, rem = i - c*TS4, ry = rem/TW, rx = rem - ry*TW;
    int gy = r0 - 1 + ry, gx = rx - 1;
    s_bl[i] = ((unsigned)gy < 64u && (unsigned)gx < 64u)
              ? out[OFF_BL + c*NP + gy*64 + gx] : 0.f;
  }
  for (int i = tid; i < 24*TS4; i += 256){
    int cd = i/TS4, rem = i - cd*TS4, ry = rem/TW, rx = rem - ry*TW;
    int c = cd >> 3, d = cd & 7;
    int gy = r0 - 1 + ry, gx = rx - 1;
    s_ps[i] = ((unsigned)gy < 64u && (unsigned)gx < 64u)
              ? psvs[(((bs*3 + c)*8) + d)*NP + gy*64 + gx] : 0.f;
  }
  for (int i = tid; i < 2*864; i += 256){
    int sub = i / 864, rem = i - sub*864;
    int j = rem & 15, ct = rem >> 4;
    s_w[i] = pw[(half*32 + sub*16 + j)*54 + ct];
  }
  __syncthreads();

  int ly = tid >> 6, lx = tid & 63;
  int p = (r0 + ly)*64 + lx;
  int tl = ly*TW + lx;

  #pragma unroll 1
  for (int sub = 0; sub < 2; sub++){
    int oc0 = half*32 + sub*16;
    const float* wsub = s_w + sub*864;

    float blp[16];
    #pragma unroll
    for (int j = 0; j < 16; j++) blp[j] = pb[oc0 + j];
    #pragma unroll
    for (int c = 0; c < 3; c++){
      const float* cin = s_bl + c*TS4 + tl;
      float v[9];
      #pragma unroll
      for (int ky = 0; ky < 3; ky++)
        #pragma unroll
        for (int kx = 0; kx < 3; kx++) v[ky*3+kx] = cin[ky*TW + kx];
      #pragma unroll
      for (int t = 0; t < 9; t++) fma16(blp, wsub + ((3 + c)*9 + t)*16, v[t]);
    }
    float oacc[16];
    #pragma unroll
    for (int j = 0; j < 16; j++) oacc[j] = 0.f;
    #pragma unroll 1
    for (int d = 0; d < 8; d++){
      float pv[16];
      #pragma unroll
      for (int j = 0; j < 16; j++) pv[j] = blp[j];
      #pragma unroll
      for (int c = 0; c < 3; c++){
        const float* cin = s_ps + (c*8 + d)*TS4 + tl;
        float v[9];
        #pragma unroll
        for (int ky = 0; ky < 3; ky++)
          #pragma unroll
          for (int kx = 0; kx < 3; kx++) v[ky*3+kx] = cin[ky*TW + kx];
        #pragma unroll
        for (int t = 0; t < 9; t++) fma16(pv, wsub + (c*9 + t)*16, v[t]);
      }
      #pragma unroll
      for (int j = 0; j < 16; j++) oacc[j] += fmaxf(pv[j], 0.f);
    }
    #pragma unroll
    for (int j = 0; j < 16; j++)
      g_psv[(bs*CN + oc0 + j)*NP + p] = oacc[j] * 0.125f;
  }
}

// ---------------------------------------------------------------------------
// K5: vref conv 515->3, ic-chunked (12). mode 0: z=1+by (ictx-only chunks,
// depends only on k_epi). mode 1: z=0 or 20+by (blended/psv chunks).
// grid (16, 20|23), block 256.
// ---------------------------------------------------------------------------
__global__ void __launch_bounds__(256) k_vref(
    const float* __restrict__ vw, const float* __restrict__ vb,
    const float* __restrict__ out, int mode){
  __shared__ float s_in[VCHUNK*TS4];
  __shared__ __align__(16) float s_w[VCHUNK*9*4];
  int rc = blockIdx.x;
  int z = (mode == 0) ? (1 + blockIdx.y)
                      : ((blockIdx.y == 0) ? 0 : 20 + blockIdx.y);
  int tid = threadIdx.x, r0 = rc*4;
  int ic0 = z*VCHUNK;
  int nch = min(VCHUNK, 515 - ic0);

  for (int i = tid; i < nch*TS4; i += 256){
    int c = i/TS4, rem = i - c*TS4, ry = rem/TW, rx = rem - ry*TW;
    int ic = ic0 + c;
    int gy = r0 - 1 + ry, gx = rx - 1;
    float v = 0.f;
    if ((unsigned)gy < 64u && (unsigned)gx < 64u){
      const float* src = (ic < 3)   ? out + OFF_BL + ic*NP
                       : (ic < 259) ? g_ictx + (ic - 3)*NP
                                    : g_psv  + (ic - 259)*NP;
      v = src[gy*64 + gx];
    }
    s_in[i] = v;
  }
  for (int i = tid; i < nch*9*4; i += 256){
    int oc = i & 3, ct = i >> 2;
    s_w[i] = (oc < 3) ? vw[(oc*515 + ic0)*9 + ct] : 0.f;
  }
  __syncthreads();

  int ly = tid >> 6, lx = tid & 63;
  int p = (r0 + ly)*64 + lx;
  int tl = ly*TW + lx;
  float acc0 = (z == 0) ? vb[0] : 0.f;
  float acc1 = (z == 0) ? vb[1] : 0.f;
  float acc2 = (z == 0) ? vb[2] : 0.f;
  #pragma unroll 1
  for (int c = 0; c < nch; c++){
    const float* cin = s_in + c*TS4 + tl;
    float v[9];
    #pragma unroll
    for (int ky = 0; ky < 3; ky++)
      #pragma unroll
      for (int kx = 0; kx < 3; kx++) v[ky*3+kx] = cin[ky*TW + kx];
    #pragma unroll
    for (int t = 0; t < 9; t++){
      float4 w = *(const float4*)(s_w + (c*9 + t)*4);
      acc0 = fmaf(w.x, v[t], acc0);
      acc1 = fmaf(w.y, v[t], acc1);
      acc2 = fmaf(w.z, v[t], acc2);
    }
  }
  g_vpart[(z*3 + 0)*NP + p] = acc0;
  g_vpart[(z*3 + 1)*NP + p] = acc1;
  g_vpart[(z*3 + 2)*NP + p] = acc2;
}

__global__ void __launch_bounds__(128) k_vfin(float* __restrict__ out){
  int i = blockIdx.x*128 + threadIdx.x;   // 0..12287
  float a = 0.f;
  #pragma unroll
  for (int z = 0; z < NVCH; z++) a += g_vpart[z*3*NP + i];
  out[OFF_R0 + i] = a;
}

// ---------------------------------------------------------------------------
// Side stream + events, created at static init.
// ---------------------------------------------------------------------------
struct HxAsync {
  cudaStream_t s1;
  cudaEvent_t e_root, e_ctx, e_epi, e_vA;
  HxAsync(){
    cudaStreamCreateWithFlags(&s1, cudaStreamNonBlocking);
    cudaEventCreateWithFlags(&e_root, cudaEventDisableTiming);
    cudaEventCreateWithFlags(&e_ctx,  cudaEventDisableTiming);
    cudaEventCreateWithFlags(&e_epi,  cudaEventDisableTiming);
    cudaEventCreateWithFlags(&e_vA,   cudaEventDisableTiming);
  }
};
static HxAsync hx;

// ---------------------------------------------------------------------------
extern "C" void kernel_launch(void* const* d_in, const int* in_sizes, int n_in,
                              void* d_out, int out_size){
  const float* sv   = (const float*)d_in[0];
  const float* sf   = (const float*)d_in[1];
  const float* psvs = (const float*)d_in[2];
  const float* wv   = (const float*)d_in[3];
  const int*   nxy  = (const int*)  d_in[5];
  const float* spa  = (const float*)d_in[6];
  const float* ang  = (const float*)d_in[7];
  const float* flow_w = (const float*)d_in[9];
  const float* flow_b = (const float*)d_in[10];
  const float* ctx_w  = (const float*)d_in[11];
  const float* ctx_b  = (const float*)d_in[12];
  const float* wnet_w = (const float*)d_in[13];
  const float* wnet_b = (const float*)d_in[14];
  const float* cnet_w = (const float*)d_in[15];
  const float* cnet_b = (const float*)d_in[16];
  const float* psv_w  = (const float*)d_in[17];
  const float* psv_b  = (const float*)d_in[18];
  const float* vref_w = (const float*)d_in[19];
  const float* vref_b = (const float*)d_in[20];
  float* out = (float*)d_out;
  cudaStream_t s0 = (cudaStream_t)0;

  // fork: ctx runs concurrently with flow on side stream
  cudaEventRecord(hx.e_root, s0);
  cudaStreamWaitEvent(hx.s1, hx.e_root, 0);

  k_flow<<<dim3(16, 2, 4), 256, 0, s0>>>(sf, sv, wv, flow_w, flow_b,
                                         wnet_w, cnet_w);
  k_ctx <<<dim3(16, 2, 4), 256, 0, hx.s1>>>(sv, ctx_w, ctx_b);

  // join: epi needs both flow (s0 order) and ctx
  cudaEventRecord(hx.e_ctx, hx.s1);
  cudaStreamWaitEvent(s0, hx.e_ctx, 0);
  k_epi<<<2048, 256, 0, s0>>>(nxy, spa, ang, wnet_w, wnet_b, cnet_w, cnet_b, out);

  // fork: vref ictx-chunks (z=1..20) depend only on epi; run beside blend/psv
  cudaEventRecord(hx.e_epi, s0);
  cudaStreamWaitEvent(hx.s1, hx.e_epi, 0);
  k_vref<<<dim3(16, 20), 256, 0, hx.s1>>>(vref_w, vref_b, out, 0);

  k_blend<<<16, 256, 0, s0>>>(out);
  k_psv  <<<dim3(16, 2, 4), 256, 0, s0>>>(psvs, psv_w, psv_b, out);
  k_vref <<<dim3(16, 23), 256, 0, s0>>>(vref_w, vref_b, out, 1);

  // join: vfin needs all 43 partials
  cudaEventRecord(hx.e_vA, hx.s1);
  cudaStreamWaitEvent(s0, hx.e_vA, 0);
  k_vfin<<<96, 128, 0, s0>>>(out);
}